// round 9
// baseline (speedup 1.0000x reference)
#include <cuda_runtime.h>
#include <cuda_bf16.h>
#include <cstdint>

// -------- scratch (device globals; no allocation allowed) --------
#define NMAX 100000
#define EMAX 1600000
#define NB_MAX 128            // ceil(NMAX/1024) = 98 <= 128

__device__ __align__(16) float g_mean[(size_t)NMAX * 32]; // mean of neighbor x rows
__device__ __align__(16) float g_z2[(size_t)NMAX * 16];   // h @ W2l
__device__ __align__(16) float g_r2[(size_t)NMAX * 16];   // h @ W2r + b2
__device__ int g_rowptr[NMAX];     // partial (per-1024-block exclusive)
__device__ int g_cnt[NMAX];
__device__ int g_cursor[NMAX];
__device__ int g_csr_src[EMAX];
__device__ int g_bsum[NB_MAX];
__device__ int g_is64;

// Shared-memory re-scan of bsum -> inclusive prefix in sboff.
// boff_excl(w) = (w>0) ? sboff[w-1] : 0. Requires blockDim.x >= NB_MAX.
__device__ __forceinline__ void block_scan_bsum(const int* __restrict__ bsum,
                                                int* sboff, int nb) {
    if (threadIdx.x < NB_MAX)
        sboff[threadIdx.x] = (threadIdx.x < nb) ? bsum[threadIdx.x] : 0;
    __syncthreads();
    for (int off = 1; off < NB_MAX; off <<= 1) {
        int t = (threadIdx.x < NB_MAX && threadIdx.x >= off) ? sboff[threadIdx.x - off] : 0;
        __syncthreads();
        if (threadIdx.x < NB_MAX) sboff[threadIdx.x] += t;
        __syncthreads();
    }
}

// -------- zero cnt+cursor + sniff dtype (block 0) --------
__global__ void zero_sniff_kernel(int* __restrict__ cnt, int* __restrict__ cursor,
                                  int n, const unsigned int* __restrict__ w,
                                  int nsamples) {
    int i = blockIdx.x * blockDim.x + threadIdx.x;
    if (i < n) { cnt[i] = 0; cursor[i] = 0; }
    if (blockIdx.x == 0) {
        int nz = 0;
        for (int k = threadIdx.x; k < nsamples; k += blockDim.x)
            nz |= (w[2 * k + 1] != 0u) ? 1 : 0;
        nz = __syncthreads_or(nz);
        if (threadIdx.x == 0) g_is64 = nz ? 0 : 1;
    }
}

// -------- count in-degree (vectorized pair reads) --------
__global__ void count_kernel(const void* __restrict__ ei,
                             int* __restrict__ cnt, int E, int N) {
    int is64 = g_is64;
    int stride = gridDim.x * blockDim.x;
    int P = E >> 1;   // E even
    if (is64) {
        const longlong2* p = (const longlong2*)((const long long*)ei + E);
        for (int i = blockIdx.x * blockDim.x + threadIdx.x; i < P; i += stride) {
            longlong2 v = p[i];
            int d0 = (int)v.x, d1 = (int)v.y;
            if (d0 >= 0 && d0 < N) atomicAdd(&cnt[d0], 1);
            if (d1 >= 0 && d1 < N) atomicAdd(&cnt[d1], 1);
        }
    } else {
        const int2* p = (const int2*)((const int*)ei + E);
        for (int i = blockIdx.x * blockDim.x + threadIdx.x; i < P; i += stride) {
            int2 v = p[i];
            if (v.x >= 0 && v.x < N) atomicAdd(&cnt[v.x], 1);
            if (v.y >= 0 && v.y < N) atomicAdd(&cnt[v.y], 1);
        }
    }
}

// -------- scan stage 1: per-1024-block exclusive scan + block totals --------
__global__ void scan1_kernel(const int* __restrict__ cnt,
                             int* __restrict__ rowptr,
                             int* __restrict__ bsum, int N) {
    __shared__ int sh[1024];
    int gid = blockIdx.x * 1024 + threadIdx.x;
    int v = (gid < N) ? cnt[gid] : 0;
    sh[threadIdx.x] = v;
    __syncthreads();
    for (int off = 1; off < 1024; off <<= 1) {
        int t = (threadIdx.x >= off) ? sh[threadIdx.x - off] : 0;
        __syncthreads();
        sh[threadIdx.x] += t;
        __syncthreads();
    }
    if (gid < N) rowptr[gid] = sh[threadIdx.x] - v;   // exclusive within block
    if (threadIdx.x == 1023) bsum[blockIdx.x] = sh[1023];
}

// -------- fill CSR (applies block offsets inline via smem scan) --------
__global__ void fill_kernel(const void* __restrict__ ei,
                            const int* __restrict__ rowptr,
                            const int* __restrict__ bsum,
                            int* __restrict__ cursor,
                            int* __restrict__ csr_src, int E, int N, int nb) {
    __shared__ int sboff[NB_MAX];
    block_scan_bsum(bsum, sboff, nb);

    int is64 = g_is64;
    int stride = gridDim.x * blockDim.x;
    int P = E >> 1;
    if (is64) {
        const longlong2* ps = (const longlong2*)ei;
        const longlong2* pd = (const longlong2*)((const long long*)ei + E);
        for (int i = blockIdx.x * blockDim.x + threadIdx.x; i < P; i += stride) {
            longlong2 sv = ps[i], dv = pd[i];
            int s0 = (int)sv.x, s1 = (int)sv.y;
            int d0 = (int)dv.x, d1 = (int)dv.y;
            if (d0 >= 0 && d0 < N) {
                int w = d0 >> 10;
                int base = rowptr[d0] + ((w > 0) ? sboff[w - 1] : 0);
                int pos = atomicAdd(&cursor[d0], 1);
                csr_src[base + pos] = s0;
            }
            if (d1 >= 0 && d1 < N) {
                int w = d1 >> 10;
                int base = rowptr[d1] + ((w > 0) ? sboff[w - 1] : 0);
                int pos = atomicAdd(&cursor[d1], 1);
                csr_src[base + pos] = s1;
            }
        }
    } else {
        const int2* ps = (const int2*)ei;
        const int2* pd = (const int2*)((const int*)ei + E);
        for (int i = blockIdx.x * blockDim.x + threadIdx.x; i < P; i += stride) {
            int2 sv = ps[i], dv = pd[i];
            if (dv.x >= 0 && dv.x < N) {
                int w = dv.x >> 10;
                int base = rowptr[dv.x] + ((w > 0) ? sboff[w - 1] : 0);
                int pos = atomicAdd(&cursor[dv.x], 1);
                csr_src[base + pos] = sv.x;
            }
            if (dv.y >= 0 && dv.y < N) {
                int w = dv.y >> 10;
                int base = rowptr[dv.y] + ((w > 0) ? sboff[w - 1] : 0);
                int pos = atomicAdd(&cursor[dv.y], 1);
                csr_src[base + pos] = sv.y;
            }
        }
    }
}

// -------- gather 1: mean[n] = (1/deg) * sum_{s in N(n)} x[s]   (rows 128B) --------
// Warp per node. 4 groups x 8 lanes; stride 16 -> 16 rows in flight per warp.
__global__ void gather1_kernel(const float* __restrict__ x,
                               const int* __restrict__ rowptr,
                               const int* __restrict__ bsum,
                               const int* __restrict__ csr_src,
                               float* __restrict__ mean, int N, int E, int nb) {
    __shared__ int sboff[NB_MAX];
    block_scan_bsum(bsum, sboff, nb);

    int lane = threadIdx.x & 31;
    int g = lane >> 3;          // 0..3
    int c = lane & 7;           // 0..7
    int n = blockIdx.x * (blockDim.x >> 5) + (threadIdx.x >> 5);
    if (n >= N) return;

    int w0 = n >> 10;
    int s0 = rowptr[n] + ((w0 > 0) ? sboff[w0 - 1] : 0);
    int s1;
    if (n + 1 < N) {
        int w1 = (n + 1) >> 10;
        s1 = rowptr[n + 1] + ((w1 > 0) ? sboff[w1 - 1] : 0);
    } else {
        s1 = E;
    }
    int deg = s1 - s0;

    float4 a0 = make_float4(0.f, 0.f, 0.f, 0.f);
    float4 a1 = make_float4(0.f, 0.f, 0.f, 0.f);
    float4 a2 = make_float4(0.f, 0.f, 0.f, 0.f);
    float4 a3 = make_float4(0.f, 0.f, 0.f, 0.f);
    for (int e = s0; e < s1; e += 16) {         // warp-uniform bound
        int i0 = e + g, i1 = e + 4 + g, i2 = e + 8 + g, i3 = e + 12 + g;
        bool v0 = i0 < s1, v1 = i1 < s1, v2 = i2 < s1, v3 = i3 < s1;
        int sid0 = v0 ? csr_src[i0] : 0;
        int sid1 = v1 ? csr_src[i1] : 0;
        int sid2 = v2 ? csr_src[i2] : 0;
        int sid3 = v3 ? csr_src[i3] : 0;
        float4 r0 = ((const float4*)(x + (size_t)sid0 * 32))[c];
        float4 r1 = ((const float4*)(x + (size_t)sid1 * 32))[c];
        float4 r2 = ((const float4*)(x + (size_t)sid2 * 32))[c];
        float4 r3 = ((const float4*)(x + (size_t)sid3 * 32))[c];
        if (v0) { a0.x += r0.x; a0.y += r0.y; a0.z += r0.z; a0.w += r0.w; }
        if (v1) { a1.x += r1.x; a1.y += r1.y; a1.z += r1.z; a1.w += r1.w; }
        if (v2) { a2.x += r2.x; a2.y += r2.y; a2.z += r2.z; a2.w += r2.w; }
        if (v3) { a3.x += r3.x; a3.y += r3.y; a3.z += r3.z; a3.w += r3.w; }
    }
    a0.x += a1.x; a0.y += a1.y; a0.z += a1.z; a0.w += a1.w;
    a2.x += a3.x; a2.y += a3.y; a2.z += a3.z; a2.w += a3.w;
    a0.x += a2.x; a0.y += a2.y; a0.z += a2.z; a0.w += a2.w;
    // reduce across 4 groups (xor 8, 16)
#pragma unroll
    for (int s = 8; s <= 16; s <<= 1) {
        a0.x += __shfl_xor_sync(0xffffffffu, a0.x, s);
        a0.y += __shfl_xor_sync(0xffffffffu, a0.y, s);
        a0.z += __shfl_xor_sync(0xffffffffu, a0.z, s);
        a0.w += __shfl_xor_sync(0xffffffffu, a0.w, s);
    }
    if (g == 0) {
        float inv = 1.0f / (float)max(deg, 1);
        float4 m = make_float4(a0.x * inv, a0.y * inv, a0.z * inv, a0.w * inv);
        ((float4*)(mean + (size_t)n * 32))[c] = m;
    }
}

// -------- fused dense: h = relu(mean@W1l + x@W1r + b1); z2 = h@W2l; r2 = h@W2r + b2 --------
__global__ void dense_kernel(const float* __restrict__ x,
                             const float* __restrict__ mean,
                             const float* __restrict__ W1l,
                             const float* __restrict__ W1r,
                             const float* __restrict__ b1,
                             const float* __restrict__ W2l,
                             const float* __restrict__ W2r,
                             const float* __restrict__ b2,
                             float* __restrict__ z2,
                             float* __restrict__ r2, int N) {
    int lane = threadIdx.x & 31;
    int warp = (blockIdx.x * blockDim.x + threadIdx.x) >> 5;
    int nwarps = (gridDim.x * blockDim.x) >> 5;

    float wl1[32], wr1[32], w2[32];
#pragma unroll
    for (int k = 0; k < 32; k++) {
        wl1[k] = W1l[k * 32 + lane];
        wr1[k] = W1r[k * 32 + lane];
    }
    int j = lane & 15;
    bool left = lane < 16;
#pragma unroll
    for (int k = 0; k < 32; k++)
        w2[k] = left ? W2l[k * 16 + j] : W2r[k * 16 + j];
    float b1j = b1[lane];
    float b2j = left ? 0.0f : b2[j];

    for (int n = warp; n < N; n += nwarps) {
        float mv = mean[(size_t)n * 32 + lane];
        float xv = x[(size_t)n * 32 + lane];

        float r = b1j;
#pragma unroll
        for (int k = 0; k < 32; k++) {
            float mk = __shfl_sync(0xffffffffu, mv, k);
            float xk = __shfl_sync(0xffffffffu, xv, k);
            r = fmaf(mk, wl1[k], fmaf(xk, wr1[k], r));
        }
        float h = fmaxf(r, 0.0f);

        float acc = b2j;
#pragma unroll
        for (int k = 0; k < 32; k++) {
            float hk = __shfl_sync(0xffffffffu, h, k);
            acc = fmaf(hk, w2[k], acc);
        }
        if (left) z2[(size_t)n * 16 + j] = acc;
        else      r2[(size_t)n * 16 + j] = acc;
    }
}

// -------- gather 2: out[n] = (1/deg) * sum_{s} z2[s] + r2[n]   (rows 64B) --------
// Warp per node. 8 groups x 4 lanes; stride 32 -> 32 rows in flight per warp.
__global__ void gather2_kernel(const float* __restrict__ z2,
                               const float* __restrict__ r2,
                               const int* __restrict__ rowptr,
                               const int* __restrict__ bsum,
                               const int* __restrict__ csr_src,
                               float* __restrict__ out, int N, int E, int nb) {
    __shared__ int sboff[NB_MAX];
    block_scan_bsum(bsum, sboff, nb);

    int lane = threadIdx.x & 31;
    int g = lane >> 2;          // 0..7
    int c = lane & 3;           // 0..3
    int n = blockIdx.x * (blockDim.x >> 5) + (threadIdx.x >> 5);
    if (n >= N) return;

    int w0 = n >> 10;
    int s0 = rowptr[n] + ((w0 > 0) ? sboff[w0 - 1] : 0);
    int s1;
    if (n + 1 < N) {
        int w1 = (n + 1) >> 10;
        s1 = rowptr[n + 1] + ((w1 > 0) ? sboff[w1 - 1] : 0);
    } else {
        s1 = E;
    }
    int deg = s1 - s0;

    float4 a0 = make_float4(0.f, 0.f, 0.f, 0.f);
    float4 a1 = make_float4(0.f, 0.f, 0.f, 0.f);
    float4 a2 = make_float4(0.f, 0.f, 0.f, 0.f);
    float4 a3 = make_float4(0.f, 0.f, 0.f, 0.f);
    for (int e = s0; e < s1; e += 32) {        // warp-uniform bound
        int i0 = e + g, i1 = e + 8 + g, i2 = e + 16 + g, i3 = e + 24 + g;
        bool v0 = i0 < s1, v1 = i1 < s1, v2 = i2 < s1, v3 = i3 < s1;
        int sid0 = v0 ? csr_src[i0] : 0;
        int sid1 = v1 ? csr_src[i1] : 0;
        int sid2 = v2 ? csr_src[i2] : 0;
        int sid3 = v3 ? csr_src[i3] : 0;
        float4 r0 = ((const float4*)(z2 + (size_t)sid0 * 16))[c];
        float4 r1 = ((const float4*)(z2 + (size_t)sid1 * 16))[c];
        float4 r2v = ((const float4*)(z2 + (size_t)sid2 * 16))[c];
        float4 r3 = ((const float4*)(z2 + (size_t)sid3 * 16))[c];
        if (v0) { a0.x += r0.x; a0.y += r0.y; a0.z += r0.z; a0.w += r0.w; }
        if (v1) { a1.x += r1.x; a1.y += r1.y; a1.z += r1.z; a1.w += r1.w; }
        if (v2) { a2.x += r2v.x; a2.y += r2v.y; a2.z += r2v.z; a2.w += r2v.w; }
        if (v3) { a3.x += r3.x; a3.y += r3.y; a3.z += r3.z; a3.w += r3.w; }
    }
    a0.x += a1.x; a0.y += a1.y; a0.z += a1.z; a0.w += a1.w;
    a2.x += a3.x; a2.y += a3.y; a2.z += a3.z; a2.w += a3.w;
    a0.x += a2.x; a0.y += a2.y; a0.z += a2.z; a0.w += a2.w;
#pragma unroll
    for (int s = 4; s <= 16; s <<= 1) {
        a0.x += __shfl_xor_sync(0xffffffffu, a0.x, s);
        a0.y += __shfl_xor_sync(0xffffffffu, a0.y, s);
        a0.z += __shfl_xor_sync(0xffffffffu, a0.z, s);
        a0.w += __shfl_xor_sync(0xffffffffu, a0.w, s);
    }
    if (g == 0) {
        float inv = 1.0f / (float)max(deg, 1);
        float4 rr = ((const float4*)(r2 + (size_t)n * 16))[c];
        float4 o = make_float4(a0.x * inv + rr.x, a0.y * inv + rr.y,
                               a0.z * inv + rr.z, a0.w * inv + rr.w);
        ((float4*)(out + (size_t)n * 16))[c] = o;
    }
}

extern "C" void kernel_launch(void* const* d_in, const int* in_sizes, int n_in,
                              void* d_out, int out_size) {
    const float* x   = (const float*)d_in[0];
    const void*  ei  = d_in[1];
    const float* W1l = (const float*)d_in[2];
    const float* W1r = (const float*)d_in[3];
    const float* b1  = (const float*)d_in[4];
    const float* W2l = (const float*)d_in[5];
    const float* W2r = (const float*)d_in[6];
    const float* b2  = (const float*)d_in[7];
    float* out = (float*)d_out;

    int N = in_sizes[0] / 32;   // 100000
    int E = in_sizes[1] / 2;    // 1600000

    float *mean, *z2, *r2;
    int *rowptr, *cnt, *cursor, *csr_src, *bsum;
    cudaGetSymbolAddress((void**)&mean, g_mean);
    cudaGetSymbolAddress((void**)&z2, g_z2);
    cudaGetSymbolAddress((void**)&r2, g_r2);
    cudaGetSymbolAddress((void**)&rowptr, g_rowptr);
    cudaGetSymbolAddress((void**)&cnt, g_cnt);
    cudaGetSymbolAddress((void**)&cursor, g_cursor);
    cudaGetSymbolAddress((void**)&csr_src, g_csr_src);
    cudaGetSymbolAddress((void**)&bsum, g_bsum);

    int nb = (N + 1023) / 1024;           // 98
    int gblocks = (N + 7) / 8;            // 8 warps per 256-thread block

    // ---- CSR build (4 launches) ----
    zero_sniff_kernel<<<(N + 255) / 256, 256>>>(cnt, cursor, N,
                                                (const unsigned int*)ei, 4096);
    count_kernel<<<2048, 256>>>(ei, cnt, E, N);
    scan1_kernel<<<nb, 1024>>>(cnt, rowptr, bsum, N);
    fill_kernel<<<2048, 256>>>(ei, rowptr, bsum, cursor, csr_src, E, N, nb);

    // ---- layer 1 gather ----
    gather1_kernel<<<gblocks, 256>>>(x, rowptr, bsum, csr_src, mean, N, E, nb);
    // ---- fused dense ----
    dense_kernel<<<2048, 256>>>(x, mean, W1l, W1r, b1, W2l, W2r, b2, z2, r2, N);
    // ---- layer 2 gather + epilogue ----
    gather2_kernel<<<gblocks, 256>>>(z2, r2, rowptr, bsum, csr_src, out, N, E, nb);
}

// round 10
// speedup vs baseline: 1.2048x; 1.2048x over previous
#include <cuda_runtime.h>
#include <cuda_bf16.h>
#include <cstdint>

// -------- scratch (device globals; no allocation allowed) --------
#define NMAX 100000

__device__ __align__(16) float g_agg1[(size_t)NMAX * 32]; // sum of neighbor x rows
__device__ __align__(16) float g_agg2[(size_t)NMAX * 16]; // sum of neighbor z2 rows
__device__ __align__(16) float g_z2[(size_t)NMAX * 16];   // h @ W2l
__device__ __align__(16) float g_r2[(size_t)NMAX * 16];   // h @ W2r + b2
__device__ float g_deg[NMAX];
__device__ int g_is64;

// -------- zero agg1/agg2/deg + sniff dtype (block 0) --------
__global__ void zero_sniff_kernel(float4* __restrict__ agg1, size_t n1,
                                  float4* __restrict__ agg2, size_t n2,
                                  float* __restrict__ deg, int nd,
                                  const unsigned int* __restrict__ w,
                                  int nsamples) {
    size_t i = (size_t)blockIdx.x * blockDim.x + threadIdx.x;
    size_t stride = (size_t)gridDim.x * blockDim.x;
    float4 z = make_float4(0.f, 0.f, 0.f, 0.f);
    for (size_t k = i; k < n1; k += stride) agg1[k] = z;
    for (size_t k = i; k < n2; k += stride) agg2[k] = z;
    for (size_t k = i; k < (size_t)nd; k += stride) deg[k] = 0.0f;
    if (blockIdx.x == 0) {
        int nz = 0;
        for (int k = threadIdx.x; k < nsamples; k += blockDim.x)
            nz |= (w[2 * k + 1] != 0u) ? 1 : 0;
        nz = __syncthreads_or(nz);
        if (threadIdx.x == 0) g_is64 = nz ? 0 : 1;
    }
}

// -------- scatter layer 1: agg1[dst] += x[src] (128B rows), deg[dst] += 1 --------
// 8 threads per edge; thread (e, c) handles float4 chunk c. Adjacent lanes in
// a group read a contiguous 128B row (coalesced). Vector RED.128 per chunk.
__global__ void scatter1_kernel(const float* __restrict__ x,
                                const void* __restrict__ ei,
                                float* __restrict__ agg1,
                                float* __restrict__ deg,
                                int E, int N) {
    int is64 = g_is64;
    long long i = (long long)blockIdx.x * blockDim.x + threadIdx.x;
    long long total = (long long)E * 8;
    if (i >= total) return;
    int e = (int)(i >> 3);
    int c = (int)(i & 7);
    int s, d;
    if (is64) {
        const long long* p = (const long long*)ei;
        s = (int)p[e]; d = (int)p[e + E];
    } else {
        const int* p = (const int*)ei;
        s = p[e]; d = p[e + E];
    }
    // indices are valid node ids (verified dtype); cheap insurance clamp
    s = min(max(s, 0), N - 1);
    d = min(max(d, 0), N - 1);
    float4 v = ((const float4*)(x + (size_t)s * 32))[c];
    atomicAdd((float4*)(agg1 + (size_t)d * 32 + (size_t)c * 4), v);
    if (c == 0) atomicAdd(&deg[d], 1.0f);
}

// -------- fused dense: mean = agg1/deg; h = relu(mean@W1l + x@W1r + b1);
//          z2 = h@W2l; r2 = h@W2r + b2 --------
__global__ void dense_kernel(const float* __restrict__ x,
                             const float* __restrict__ agg1,
                             const float* __restrict__ deg,
                             const float* __restrict__ W1l,
                             const float* __restrict__ W1r,
                             const float* __restrict__ b1,
                             const float* __restrict__ W2l,
                             const float* __restrict__ W2r,
                             const float* __restrict__ b2,
                             float* __restrict__ z2,
                             float* __restrict__ r2, int N) {
    int lane = threadIdx.x & 31;
    int warp = (blockIdx.x * blockDim.x + threadIdx.x) >> 5;
    int nwarps = (gridDim.x * blockDim.x) >> 5;

    float wl1[32], wr1[32], w2[32];
#pragma unroll
    for (int k = 0; k < 32; k++) {
        wl1[k] = W1l[k * 32 + lane];
        wr1[k] = W1r[k * 32 + lane];
    }
    int j = lane & 15;
    bool left = lane < 16;
#pragma unroll
    for (int k = 0; k < 32; k++)
        w2[k] = left ? W2l[k * 16 + j] : W2r[k * 16 + j];
    float b1j = b1[lane];
    float b2j = left ? 0.0f : b2[j];

    for (int n = warp; n < N; n += nwarps) {
        float inv = 1.0f / fmaxf(deg[n], 1.0f);
        float mv = agg1[(size_t)n * 32 + lane] * inv;
        float xv = x[(size_t)n * 32 + lane];

        float r = b1j;
#pragma unroll
        for (int k = 0; k < 32; k++) {
            float mk = __shfl_sync(0xffffffffu, mv, k);
            float xk = __shfl_sync(0xffffffffu, xv, k);
            r = fmaf(mk, wl1[k], fmaf(xk, wr1[k], r));
        }
        float h = fmaxf(r, 0.0f);

        float acc = b2j;
#pragma unroll
        for (int k = 0; k < 32; k++) {
            float hk = __shfl_sync(0xffffffffu, h, k);
            acc = fmaf(hk, w2[k], acc);
        }
        if (left) z2[(size_t)n * 16 + j] = acc;
        else      r2[(size_t)n * 16 + j] = acc;
    }
}

// -------- scatter layer 2: agg2[dst] += z2[src] (64B rows) --------
// 4 threads per edge; thread (e, c) handles float4 chunk c.
__global__ void scatter2_kernel(const float* __restrict__ z2,
                                const void* __restrict__ ei,
                                float* __restrict__ agg2,
                                int E, int N) {
    int is64 = g_is64;
    long long i = (long long)blockIdx.x * blockDim.x + threadIdx.x;
    long long total = (long long)E * 4;
    if (i >= total) return;
    int e = (int)(i >> 2);
    int c = (int)(i & 3);
    int s, d;
    if (is64) {
        const long long* p = (const long long*)ei;
        s = (int)p[e]; d = (int)p[e + E];
    } else {
        const int* p = (const int*)ei;
        s = p[e]; d = p[e + E];
    }
    s = min(max(s, 0), N - 1);
    d = min(max(d, 0), N - 1);
    float4 v = ((const float4*)(z2 + (size_t)s * 16))[c];
    atomicAdd((float4*)(agg2 + (size_t)d * 16 + (size_t)c * 4), v);
}

// -------- epilogue: out[n] = agg2[n]/max(deg,1) + r2[n]  (N x 16) --------
__global__ void epilogue_kernel(const float* __restrict__ agg2,
                                const float* __restrict__ r2,
                                const float* __restrict__ deg,
                                float* __restrict__ out, int N) {
    int i = blockIdx.x * blockDim.x + threadIdx.x;   // one float4 per thread
    int total = N * 4;
    if (i >= total) return;
    int n = i >> 2;
    float inv = 1.0f / fmaxf(deg[n], 1.0f);
    float4 a = ((const float4*)agg2)[i];
    float4 rr = ((const float4*)r2)[i];
    float4 o = make_float4(a.x * inv + rr.x, a.y * inv + rr.y,
                           a.z * inv + rr.z, a.w * inv + rr.w);
    ((float4*)out)[i] = o;
}

extern "C" void kernel_launch(void* const* d_in, const int* in_sizes, int n_in,
                              void* d_out, int out_size) {
    const float* x   = (const float*)d_in[0];
    const void*  ei  = d_in[1];
    const float* W1l = (const float*)d_in[2];
    const float* W1r = (const float*)d_in[3];
    const float* b1  = (const float*)d_in[4];
    const float* W2l = (const float*)d_in[5];
    const float* W2r = (const float*)d_in[6];
    const float* b2  = (const float*)d_in[7];
    float* out = (float*)d_out;

    int N = in_sizes[0] / 32;   // 100000
    int E = in_sizes[1] / 2;    // 1600000

    float *agg1, *agg2, *z2, *r2, *deg;
    cudaGetSymbolAddress((void**)&agg1, g_agg1);
    cudaGetSymbolAddress((void**)&agg2, g_agg2);
    cudaGetSymbolAddress((void**)&z2, g_z2);
    cudaGetSymbolAddress((void**)&r2, g_r2);
    cudaGetSymbolAddress((void**)&deg, g_deg);

    size_t n1 = (size_t)N * 32 / 4;   // agg1 float4 count
    size_t n2 = (size_t)N * 16 / 4;   // agg2 float4 count

    // 1: zero scratch + sniff dtype
    zero_sniff_kernel<<<2048, 256>>>((float4*)agg1, n1, (float4*)agg2, n2,
                                     deg, N, (const unsigned int*)ei, 4096);
    // 2: scatter layer 1 (RED.128 x8 per edge) + degree
    {
        long long total = (long long)E * 8;
        int blocks = (int)((total + 255) / 256);
        scatter1_kernel<<<blocks, 256>>>(x, ei, agg1, deg, E, N);
    }
    // 3: fused dense (layer-1 linear+relu, layer-2 transform)
    dense_kernel<<<2048, 256>>>(x, agg1, deg, W1l, W1r, b1, W2l, W2r, b2,
                                z2, r2, N);
    // 4: scatter layer 2 (RED.128 x4 per edge)
    {
        long long total = (long long)E * 4;
        int blocks = (int)((total + 255) / 256);
        scatter2_kernel<<<blocks, 256>>>(z2, ei, agg2, E, N);
    }
    // 5: epilogue
    epilogue_kernel<<<(N * 4 + 255) / 256, 256>>>(agg2, r2, deg, out, N);
}